// round 1
// baseline (speedup 1.0000x reference)
#include <cuda_runtime.h>
#include <cuda_bf16.h>
#include <cstdint>
#include <math.h>

#define N_ROWS 16384
#define DIM    512
#define SCALE  14.2857142857142857f   // 1/0.07

#define BM 128
#define BN 128
#define BK 64
#define LDA 520     // padded bf16 stride for A block (conflict-free)
#define LDB 72      // padded bf16 stride for B tile
#define NTHREADS 256

// -------- static scratch (no allocations allowed) --------
__device__ __nv_bfloat16 g_img_bf[(size_t)N_ROWS * DIM];
__device__ __nv_bfloat16 g_txt_bf[(size_t)N_ROWS * DIM];
__device__ float g_lse[2 * N_ROWS];
__device__ float g_diag[N_ROWS];

// -------- fp32 -> bf16 conversion --------
__global__ void convert_kernel(const float* __restrict__ img,
                               const float* __restrict__ txt) {
    int total = N_ROWS * DIM / 2;
    for (int i = blockIdx.x * blockDim.x + threadIdx.x; i < total;
         i += gridDim.x * blockDim.x) {
        float2 a = ((const float2*)img)[i];
        float2 b = ((const float2*)txt)[i];
        ((__nv_bfloat162*)g_img_bf)[i] = __float22bfloat162_rn(a);
        ((__nv_bfloat162*)g_txt_bf)[i] = __float22bfloat162_rn(b);
    }
}

// -------- exact fp32 diagonal: diag[r] = SCALE * <img_r, txt_r> --------
__global__ void diag_kernel(const float* __restrict__ img,
                            const float* __restrict__ txt) {
    int warp = (blockIdx.x * blockDim.x + threadIdx.x) >> 5;
    int lane = threadIdx.x & 31;
    if (warp >= N_ROWS) return;
    const float* a = img + (size_t)warp * DIM;
    const float* b = txt + (size_t)warp * DIM;
    float s = 0.f;
    #pragma unroll 4
    for (int k = lane; k < DIM; k += 32) s += a[k] * b[k];
    #pragma unroll
    for (int o = 16; o; o >>= 1) s += __shfl_xor_sync(0xFFFFFFFFu, s, o);
    if (lane == 0) g_diag[warp] = SCALE * s;
}

// -------- mma / cp.async helpers --------
__device__ __forceinline__ void mma_bf16(float* c, const uint32_t* a, const uint32_t* b) {
    asm volatile(
        "mma.sync.aligned.m16n8k16.row.col.f32.bf16.bf16.f32 "
        "{%0,%1,%2,%3}, {%4,%5,%6,%7}, {%8,%9}, {%0,%1,%2,%3};\n"
        : "+f"(c[0]), "+f"(c[1]), "+f"(c[2]), "+f"(c[3])
        : "r"(a[0]), "r"(a[1]), "r"(a[2]), "r"(a[3]),
          "r"(b[0]), "r"(b[1]));
}

__device__ __forceinline__ void cp_async16(void* smem, const void* gmem) {
    uint32_t s = (uint32_t)__cvta_generic_to_shared(smem);
    asm volatile("cp.async.cg.shared.global [%0], [%1], 16;\n" :: "r"(s), "l"(gmem));
}

// -------- fused GEMM + online logsumexp (per direction row sweep) --------
// grid.x in [0,256): dir = blockIdx.x>>7, row block = blockIdx.x & 127
extern __shared__ char smem_raw[];

__global__ void __launch_bounds__(NTHREADS, 1) gemm_lse_kernel() {
    const int dir = blockIdx.x >> 7;
    const int rb  = blockIdx.x & 127;
    const __nv_bfloat16* __restrict__ A = dir ? g_txt_bf : g_img_bf;
    const __nv_bfloat16* __restrict__ B = dir ? g_img_bf : g_txt_bf;

    __nv_bfloat16* As = (__nv_bfloat16*)smem_raw;           // BM * LDA
    __nv_bfloat16* Bs = As + BM * LDA;                       // 2 * BN * LDB
    float2* sm_merge  = (float2*)(Bs + 2 * BN * LDB);        // 128 * 4

    const int tid  = threadIdx.x;
    const int warp = tid >> 5, lane = tid & 31;
    const int warpM = warp >> 2, warpN = warp & 3;
    const int g = lane >> 2, q = lane & 3;

    // ---- load A row block (128 x 512 bf16) into smem ----
    {
        const uint4* src = (const uint4*)(A + (size_t)rb * BM * DIM);
        #pragma unroll
        for (int idx = tid; idx < BM * DIM / 8; idx += NTHREADS) {
            int row = idx >> 6, c8 = idx & 63;
            *(uint4*)(As + row * LDA + c8 * 8) = src[idx];
        }
    }

    auto load_tile = [&](int s, int buf) {
        int jt = s >> 3, kc = s & 7;
        const __nv_bfloat16* bsrc = B + (size_t)(jt * BN) * DIM + kc * BK;
        __nv_bfloat16* dst = Bs + buf * BN * LDB;
        #pragma unroll
        for (int i = tid; i < BN * 8; i += NTHREADS) {   // 1024 x 16B
            int row = i >> 3, c8 = i & 7;
            cp_async16(dst + row * LDB + c8 * 8, bsrc + (size_t)row * DIM + c8 * 8);
        }
        asm volatile("cp.async.commit_group;\n");
    };

    float acc[4][4][4];
    float m_run[8], s_run[8];
    #pragma unroll
    for (int e = 0; e < 8; e++) { m_run[e] = -INFINITY; s_run[e] = 0.f; }

    load_tile(0, 0);   // prologue

    const int NSTEPS = 128 * 8;   // 128 col tiles * 8 K-chunks
    for (int s = 0; s < NSTEPS; s++) {
        const int buf = s & 1;
        if (s + 1 < NSTEPS) {
            load_tile(s + 1, (s + 1) & 1);
            asm volatile("cp.async.wait_group 1;\n");
        } else {
            asm volatile("cp.async.wait_group 0;\n");
        }
        __syncthreads();

        const int kc = s & 7;
        if (kc == 0) {
            #pragma unroll
            for (int mt = 0; mt < 4; mt++)
                #pragma unroll
                for (int nt = 0; nt < 4; nt++)
                    #pragma unroll
                    for (int r = 0; r < 4; r++) acc[mt][nt][r] = 0.f;
        }

        const __nv_bfloat16* Bb = Bs + buf * BN * LDB;
        #pragma unroll
        for (int kk = 0; kk < 4; kk++) {
            uint32_t af[4][4], bf[4][2];
            const int cA = kc * BK + kk * 16 + q * 2;
            #pragma unroll
            for (int mt = 0; mt < 4; mt++) {
                const __nv_bfloat16* p = As + (warpM * 64 + mt * 16 + g) * LDA + cA;
                af[mt][0] = *(const uint32_t*)p;
                af[mt][1] = *(const uint32_t*)(p + 8 * LDA);
                af[mt][2] = *(const uint32_t*)(p + 8);
                af[mt][3] = *(const uint32_t*)(p + 8 * LDA + 8);
            }
            const int cB = kk * 16 + q * 2;
            #pragma unroll
            for (int nt = 0; nt < 4; nt++) {
                const __nv_bfloat16* p = Bb + (warpN * 32 + nt * 8 + g) * LDB + cB;
                bf[nt][0] = *(const uint32_t*)p;
                bf[nt][1] = *(const uint32_t*)(p + 8);
            }
            #pragma unroll
            for (int mt = 0; mt < 4; mt++)
                #pragma unroll
                for (int nt = 0; nt < 4; nt++)
                    mma_bf16(acc[mt][nt], af[mt], bf[nt]);
        }
        __syncthreads();   // protect buffer before re-fill 2 steps ahead

        // ---- epilogue: online logsumexp update once per column tile ----
        if (kc == 7) {
            #pragma unroll
            for (int mt = 0; mt < 4; mt++) {
                #pragma unroll
                for (int half = 0; half < 2; half++) {
                    const int e = mt * 2 + half;
                    float v[8];
                    #pragma unroll
                    for (int nt = 0; nt < 4; nt++) {
                        v[nt * 2]     = acc[mt][nt][half * 2]     * SCALE;
                        v[nt * 2 + 1] = acc[mt][nt][half * 2 + 1] * SCALE;
                    }
                    float tm = v[0];
                    #pragma unroll
                    for (int i = 1; i < 8; i++) tm = fmaxf(tm, v[i]);
                    const float nm = fmaxf(m_run[e], tm);
                    float ts = 0.f;
                    #pragma unroll
                    for (int i = 0; i < 8; i++) ts += __expf(v[i] - nm);
                    s_run[e] = s_run[e] * __expf(m_run[e] - nm) + ts;
                    m_run[e] = nm;
                }
            }
        }
    }

    // ---- merge across the 4 lanes sharing each row (q dimension) ----
    #pragma unroll
    for (int e = 0; e < 8; e++) {
        float m = m_run[e], sv = s_run[e];
        #pragma unroll
        for (int o = 1; o < 4; o <<= 1) {
            float mo = __shfl_xor_sync(0xFFFFFFFFu, m, o);
            float so = __shfl_xor_sync(0xFFFFFFFFu, sv, o);
            float nm = fmaxf(m, mo);
            sv = sv * __expf(m - nm) + so * __expf(mo - nm);
            m = nm;
        }
        m_run[e] = m; s_run[e] = sv;
    }

    // ---- merge across the 4 warpN copies via smem ----
    if (q == 0) {
        #pragma unroll
        for (int e = 0; e < 8; e++) {
            int r = warpM * 64 + (e >> 1) * 16 + (e & 1) * 8 + g;
            sm_merge[r * 4 + warpN] = make_float2(m_run[e], s_run[e]);
        }
    }
    __syncthreads();
    if (tid < 128) {
        float m = -INFINITY, sv = 0.f;
        #pragma unroll
        for (int w = 0; w < 4; w++) {
            float2 ms = sm_merge[tid * 4 + w];
            float nm = fmaxf(m, ms.x);
            sv = sv * __expf(m - nm) + ms.y * __expf(ms.x - nm);
            m = nm;
        }
        g_lse[dir * N_ROWS + rb * BM + tid] = m + __logf(sv);
    }
}

// -------- final scalar reduction (deterministic, fp64) --------
__global__ void final_kernel(float* __restrict__ out) {
    __shared__ double sm[256];
    double p = 0.0;
    for (int i = threadIdx.x; i < N_ROWS; i += 256)
        p += (double)g_lse[i] + (double)g_lse[N_ROWS + i] - 2.0 * (double)g_diag[i];
    sm[threadIdx.x] = p;
    __syncthreads();
    for (int o = 128; o; o >>= 1) {
        if (threadIdx.x < o) sm[threadIdx.x] += sm[threadIdx.x + o];
        __syncthreads();
    }
    if (threadIdx.x == 0) out[0] = (float)(sm[0] / (2.0 * N_ROWS));
}

extern "C" void kernel_launch(void* const* d_in, const int* in_sizes, int n_in,
                              void* d_out, int out_size) {
    const float* img = (const float*)d_in[0];
    const float* txt = (const float*)d_in[1];

    convert_kernel<<<1024, 256>>>(img, txt);
    diag_kernel<<<2048, 256>>>(img, txt);

    const size_t smem = (size_t)BM * LDA * 2      // A block
                      + (size_t)2 * BN * LDB * 2  // double-buffered B tiles
                      + 128 * 4 * sizeof(float2); // merge buffer
    cudaFuncSetAttribute(gemm_lse_kernel,
                         cudaFuncAttributeMaxDynamicSharedMemorySize, (int)smem);
    gemm_lse_kernel<<<256, NTHREADS, smem>>>();

    final_kernel<<<1, 256>>>((float*)d_out);
}

// round 3
// speedup vs baseline: 6.6492x; 6.6492x over previous
#include <cuda_runtime.h>
#include <cuda.h>
#include <cuda_bf16.h>
#include <cstdint>
#include <math.h>

#define N_ROWS 16384
#define DIM    512
#define SCALEF 14.285714285714286f
#define C1F    20.609928468897677f   /* SCALE * log2(e) */
#define LN2F   0.6931471805599453f

// ---- tcgen05 availability (a-suffix device passes only) ----
#if defined(__CUDA_ARCH__) && (defined(__CUDA_ARCH_FEAT_SM103_ALL) || defined(__CUDA_ARCH_FEAT_SM100_ALL) || defined(__CUDA_ARCH_FEAT_SM101_ALL))
#define HAS_TC 1
#else
#define HAS_TC 0
#endif

// ===== tcgen05 kernel config =====
#define NTILES 128
#define NSTAGE 4
#define NTHR   192
#define BAR_AFULL   0
#define BAR_BFULL(c)   (8  + 8*(c))
#define BAR_BEMPTY(c)  (40 + 8*(c))
#define BAR_DEMPTY(b)  (72 + 8*(b))
#define SM_TPTR     96
#define SM_A        1024
#define SM_B        (1024 + 131072)
#define SMEM_TOTAL_TC  (1024 + 131072 + NSTAGE*16384)
#define MMA_IDESC 0x10200490u   /* f32 acc, bf16 x bf16, M=256, N=128 */

// ===== fallback (mma.sync) config =====
#define FB_BM 128
#define FB_BN 128
#define FB_LDA 520
#define FB_LDB 72
#define FB_NTHR 256
#define SMEM_TOTAL_FB ((size_t)FB_BM*FB_LDA*2 + 2*FB_BN*FB_LDB*2 + 128*4*sizeof(float2))

// -------- static scratch --------
__device__ __align__(1024) __nv_bfloat16 g_img_bf[(size_t)N_ROWS * DIM];
__device__ __align__(1024) __nv_bfloat16 g_txt_bf[(size_t)N_ROWS * DIM];
__device__ float  g_lse[2 * N_ROWS];
__device__ float  g_diag[N_ROWS];
__device__ double g_part[32];

// ================= generic helpers =================
__device__ __forceinline__ float ex2f(float x) { float y; asm("ex2.approx.f32 %0, %1;" : "=f"(y) : "f"(x)); return y; }
__device__ __forceinline__ float lg2f(float x) { float y; asm("lg2.approx.f32 %0, %1;" : "=f"(y) : "f"(x)); return y; }

// ================= small kernels =================
__global__ void convert_kernel(const float* __restrict__ img, const float* __restrict__ txt) {
    int total = N_ROWS * DIM / 2;
    for (int i = blockIdx.x * blockDim.x + threadIdx.x; i < total; i += gridDim.x * blockDim.x) {
        float2 a = ((const float2*)img)[i];
        float2 b = ((const float2*)txt)[i];
        ((__nv_bfloat162*)g_img_bf)[i] = __float22bfloat162_rn(a);
        ((__nv_bfloat162*)g_txt_bf)[i] = __float22bfloat162_rn(b);
    }
}

__global__ void diag_kernel(const float* __restrict__ img, const float* __restrict__ txt) {
    int warp = (blockIdx.x * blockDim.x + threadIdx.x) >> 5;
    int lane = threadIdx.x & 31;
    if (warp >= N_ROWS) return;
    const float* a = img + (size_t)warp * DIM;
    const float* b = txt + (size_t)warp * DIM;
    float s = 0.f;
    #pragma unroll 4
    for (int k = lane; k < DIM; k += 32) s += a[k] * b[k];
    #pragma unroll
    for (int o = 16; o; o >>= 1) s += __shfl_xor_sync(0xFFFFFFFFu, s, o);
    if (lane == 0) g_diag[warp] = SCALEF * s;
}

#if HAS_TC
// ================= tcgen05-only PTX helpers =================
__device__ __forceinline__ uint32_t smem_u32(const void* p) {
    uint32_t a;
    asm("{ .reg .u64 t; cvta.to.shared.u64 t, %1; cvt.u32.u64 %0, t; }" : "=r"(a) : "l"(p));
    return a;
}
__device__ __forceinline__ uint32_t elect_one() {
    uint32_t pred;
    asm volatile("{\n\t.reg .pred p;\n\telect.sync _|p, 0xFFFFFFFF;\n\tselp.b32 %0, 1, 0, p;\n\t}" : "=r"(pred));
    return pred;
}
__device__ __forceinline__ uint32_t ctarank() {
    uint32_t r; asm("mov.u32 %0, %%cluster_ctarank;" : "=r"(r)); return r;
}

#define MBARRIER_INIT(addr, cnt) \
    asm volatile("mbarrier.init.shared.b64 [%0], %1;" :: "r"((uint32_t)(addr)), "r"((uint32_t)(cnt)) : "memory")
#define MBARRIER_EXPECT_TX(addr, bytes) \
    asm volatile("mbarrier.arrive.expect_tx.shared.b64 _, [%0], %1;" :: "r"((uint32_t)(addr)), "r"((uint32_t)(bytes)) : "memory")
#define MBARRIER_ARRIVE_LEADER(addr) \
    asm volatile("{\n\t.reg .b32 la;\n\tand.b32 la, %0, 0xFEFFFFFF;\n\t" \
                 "mbarrier.arrive.shared::cluster.b64 _, [la];\n\t}" :: "r"((uint32_t)(addr)) : "memory")
#define MBARRIER_WAIT_PARITY(addr, par) do {                                      \
    uint32_t _m = (uint32_t)(addr), _p = (uint32_t)(par), _d;                     \
    asm volatile("{\n\t.reg .pred p;\n\t"                                         \
        "mbarrier.try_wait.parity.acquire.cta.shared::cta.b64 p, [%1], %2;\n\t"   \
        "selp.b32 %0, 1, 0, p;\n\t}" : "=r"(_d) : "r"(_m), "r"(_p) : "memory");   \
    if (!_d) {                                                                    \
        asm volatile("{\n\t.reg .pred P1;\n\t"                                    \
            "WL_%=:\n\t"                                                          \
            "mbarrier.try_wait.parity.acquire.cta.shared::cta.b64 P1, [%0], %1, 0x989680;\n\t" \
            "@P1 bra.uni WD_%=;\n\t"                                              \
            "bra.uni WL_%=;\n\t"                                                  \
            "WD_%=:\n\t}" :: "r"(_m), "r"(_p) : "memory");                        \
    } } while (0)

#define CLUSTER_SYNC() do { \
    asm volatile("barrier.cluster.arrive.aligned;" ::: "memory"); \
    asm volatile("barrier.cluster.wait.aligned;"   ::: "memory"); } while (0)

#define TCGEN05_ALLOC_CG2(sm, n) \
    asm volatile("tcgen05.alloc.cta_group::2.sync.aligned.shared::cta.b32 [%0], %1;" \
                 :: "r"((uint32_t)(sm)), "r"((uint32_t)(n)) : "memory")
#define TCGEN05_DEALLOC_CG2(t, n) \
    asm volatile("tcgen05.dealloc.cta_group::2.sync.aligned.b32 %0, %1;" :: "r"(t), "r"((uint32_t)(n)))
#define TCGEN05_RELINQ_CG2() \
    asm volatile("tcgen05.relinquish_alloc_permit.cta_group::2.sync.aligned;")
#define TCGEN05_COMMIT_MC_CG2(bar, mask) \
    asm volatile("tcgen05.commit.cta_group::2.mbarrier::arrive::one.shared::cluster.multicast::cluster.b64 [%0], %1;" \
                 :: "r"((uint32_t)(bar)), "h"((uint16_t)(mask)) : "memory")
#define TCGEN05_FENCE_BEFORE() asm volatile("tcgen05.fence::before_thread_sync;" ::: "memory")
#define TCGEN05_FENCE_AFTER()  asm volatile("tcgen05.fence::after_thread_sync;" ::: "memory")
#define TCGEN05_WAIT_LD()      asm volatile("tcgen05.wait::ld.sync.aligned;" ::: "memory")

#define TCGEN05_LD_32X32B_X32(r, ta) \
    asm volatile("tcgen05.ld.sync.aligned.32x32b.x32.b32 " \
        "{%0, %1, %2, %3, %4, %5, %6, %7, %8, %9, %10, %11, %12, %13, %14, %15, " \
        " %16, %17, %18, %19, %20, %21, %22, %23, %24, %25, %26, %27, %28, %29, %30, %31}, [%32];" \
        : "=r"((r)[0]),  "=r"((r)[1]),  "=r"((r)[2]),  "=r"((r)[3]), \
          "=r"((r)[4]),  "=r"((r)[5]),  "=r"((r)[6]),  "=r"((r)[7]), \
          "=r"((r)[8]),  "=r"((r)[9]),  "=r"((r)[10]), "=r"((r)[11]), \
          "=r"((r)[12]), "=r"((r)[13]), "=r"((r)[14]), "=r"((r)[15]), \
          "=r"((r)[16]), "=r"((r)[17]), "=r"((r)[18]), "=r"((r)[19]), \
          "=r"((r)[20]), "=r"((r)[21]), "=r"((r)[22]), "=r"((r)[23]), \
          "=r"((r)[24]), "=r"((r)[25]), "=r"((r)[26]), "=r"((r)[27]), \
          "=r"((r)[28]), "=r"((r)[29]), "=r"((r)[30]), "=r"((r)[31]) \
        : "r"(ta))

#define TMA_LOAD_3D_CG2(dst, map, x, y, z, bar) \
    asm volatile("{\n\t.reg .b32 lb;\n\tand.b32 lb, %5, 0xFEFFFFFF;\n\t" \
        "cp.async.bulk.tensor.3d.cta_group::2.shared::cluster.global" \
        ".tile.mbarrier::complete_tx::bytes [%0], [%1, {%2, %3, %4}], [lb];\n\t}" \
        :: "r"((uint32_t)(dst)), "l"(map), "r"((int32_t)(x)), "r"((int32_t)(y)), "r"((int32_t)(z)), \
           "r"((uint32_t)(bar)) : "memory")

static constexpr uint64_t SMEM_DESC_BASE_SW128 =
    (uint64_t(2)  << 61) | (uint64_t(1) << 46) | (uint64_t(64) << 32) | (uint64_t(1) << 16);
#define MAKE_SMEM_DESC(a) (SMEM_DESC_BASE_SW128 | ((uint64_t)((a) >> 4) & 0x3FFF))

__device__ __forceinline__ void mma_f16_ss_cg2(uint32_t d, uint64_t a, uint64_t b,
                                               uint32_t idesc, uint32_t en) {
    asm volatile("{\n\t.reg .pred p;\n\tsetp.ne.u32 p, %5, 0;\n\t"
        "tcgen05.mma.cta_group::2.kind::f16 [%0], %1, %2, %3, "
        "{%4, %4, %4, %4, %4, %4, %4, %4}, p;\n\t}"
        :: "r"(d), "l"(a), "l"(b), "r"(idesc), "r"(0u), "r"(en) : "memory");
}
#endif  // HAS_TC device helpers

// ================= tcgen05 cg2 GEMM + online LSE =================
// grid = 256 CTAs = 128 clusters of 2.  pair = blockIdx.x>>1.
// dir = pair>>6, rb = pair&63.  Pair computes rows [rb*256, +256) vs all 16384 cols.
extern __shared__ char smem_raw_g[];

__global__ void __launch_bounds__(NTHR, 1) __cluster_dims__(2, 1, 1)
clip_gemm_tc(const __grid_constant__ CUtensorMap tm_img,
             const __grid_constant__ CUtensorMap tm_txt) {
#if HAS_TC
    uint32_t sb = smem_u32(smem_raw_g);
    const int tid  = threadIdx.x;
    const int wid  = tid >> 5;
    const int lane = tid & 31;
    const uint32_t rank = ctarank();
    const int pair = blockIdx.x >> 1;
    const int dir  = pair >> 6;
    const int rb   = pair & 63;

    if (wid == 4) TCGEN05_ALLOC_CG2(sb + SM_TPTR, 256);
    if (tid == 0) {
        MBARRIER_INIT(sb + BAR_AFULL, 1);
        #pragma unroll
        for (int c = 0; c < NSTAGE; c++) {
            MBARRIER_INIT(sb + BAR_BFULL(c), 1);
            MBARRIER_INIT(sb + BAR_BEMPTY(c), 1);
        }
        MBARRIER_INIT(sb + BAR_DEMPTY(0), 8);
        MBARRIER_INIT(sb + BAR_DEMPTY(1), 8);
    }
    __syncthreads();
    uint32_t tmem;
    asm volatile("ld.shared.b32 %0, [%1];" : "=r"(tmem) : "r"(sb + SM_TPTR));
    CLUSTER_SYNC();   // barriers visible cluster-wide before any TMA / commit

    if (wid == 4) {
        // ---------------- producer: TMA issue ----------------
        if (elect_one()) {
            const CUtensorMap* mA = dir ? &tm_txt : &tm_img;
            const CUtensorMap* mB = dir ? &tm_img : &tm_txt;
            const int arow = rb * 256 + (int)rank * 128;
            if (rank == 0) MBARRIER_EXPECT_TX(sb + BAR_AFULL, 262144);
            #pragma unroll
            for (int k8 = 0; k8 < 8; k8++)
                #pragma unroll
                for (int r64 = 0; r64 < 2; r64++)
                    TMA_LOAD_3D_CG2(sb + SM_A + k8 * 16384 + r64 * 8192, mA,
                                    k8 * 64, arow + r64 * 64, 0, sb + BAR_AFULL);
            for (int i = 0; i < NTILES * NSTAGE; i++) {
                const int t = i >> 2, c = i & 3;
                MBARRIER_WAIT_PARITY(sb + BAR_BEMPTY(c), (t & 1) ^ 1);
                if (rank == 0) MBARRIER_EXPECT_TX(sb + BAR_BFULL(c), 32768);
                const int y = t * 128 + (int)rank * 64;
                TMA_LOAD_3D_CG2(sb + SM_B + c * 16384,        mB, c * 128,      y, 0, sb + BAR_BFULL(c));
                TMA_LOAD_3D_CG2(sb + SM_B + c * 16384 + 8192, mB, c * 128 + 64, y, 0, sb + BAR_BFULL(c));
            }
        }
    } else if (wid == 5) {
        // ---------------- MMA issuer (leader only) ----------------
        if (rank == 0 && elect_one()) {
            MBARRIER_WAIT_PARITY(sb + BAR_AFULL, 0);
            const uint64_t adb = MAKE_SMEM_DESC(sb + SM_A);
            for (int t = 0; t < NTILES; t++) {
                const int b = t & 1;
                MBARRIER_WAIT_PARITY(sb + BAR_DEMPTY(b), ((t >> 1) & 1) ^ 1);
                TCGEN05_FENCE_AFTER();
                #pragma unroll
                for (int c = 0; c < NSTAGE; c++) {
                    MBARRIER_WAIT_PARITY(sb + BAR_BFULL(c), t & 1);
                    const uint64_t bdb = MAKE_SMEM_DESC(sb + SM_B + c * 16384);
                    #pragma unroll
                    for (int ks = 0; ks < 8; ks++) {
                        const int gk = c * 8 + ks;
                        mma_f16_ss_cg2(tmem + b * 128,
                                       adb + (gk >> 2) * 1024 + (gk & 3) * 2,
                                       bdb + (ks >> 2) * 512  + (ks & 3) * 2,
                                       MMA_IDESC, gk > 0);
                    }
                    // stage c reusable (both CTAs); c==3 commit also means D tile done
                    TCGEN05_COMMIT_MC_CG2(sb + BAR_BEMPTY(c), 0x3);
                }
            }
        }
    } else if (wid < 4) {
        // ---------------- epilogue: online logsumexp (log2 domain) ----------------
        float m2 = -INFINITY, sum = 0.f;
        for (int t = 0; t < NTILES; t++) {
            MBARRIER_WAIT_PARITY(sb + BAR_BEMPTY(3), t & 1);   // completion #(t+1)
            TCGEN05_FENCE_AFTER();
            const int b = t & 1;
            #pragma unroll
            for (int q = 0; q < 4; q++) {
                uint32_t r[32];
                TCGEN05_LD_32X32B_X32(r, tmem + b * 128 + q * 32);
                TCGEN05_WAIT_LD();
                float v[32], bm = -INFINITY;
                #pragma unroll
                for (int j = 0; j < 32; j++) {
                    v[j] = __uint_as_float(r[j]) * C1F;
                    bm = fmaxf(bm, v[j]);
                }
                const float mn = fmaxf(m2, bm);
                float acc = 0.f;
                #pragma unroll
                for (int j = 0; j < 32; j++) acc += ex2f(v[j] - mn);
                sum = fmaf(sum, ex2f(m2 - mn), acc);
                m2 = mn;
            }
            TCGEN05_FENCE_BEFORE();
            if (lane == 0) MBARRIER_ARRIVE_LEADER(sb + BAR_DEMPTY(b));
        }
        g_lse[dir * N_ROWS + rb * 256 + (int)rank * 128 + tid] = (m2 + lg2f(sum)) * LN2F;
    }

    __syncthreads();
    CLUSTER_SYNC();
    if (wid == 4) {
        TCGEN05_RELINQ_CG2();
        TCGEN05_DEALLOC_CG2(tmem, 256);
    }
    CLUSTER_SYNC();
#endif  // HAS_TC
}

// ================= fallback: mma.sync kernel (R1, proven) =================
__device__ __forceinline__ void mma_bf16_fb(float* c, const uint32_t* a, const uint32_t* b) {
#if defined(__CUDA_ARCH__)
    asm volatile(
        "mma.sync.aligned.m16n8k16.row.col.f32.bf16.bf16.f32 "
        "{%0,%1,%2,%3}, {%4,%5,%6,%7}, {%8,%9}, {%0,%1,%2,%3};\n"
        : "+f"(c[0]), "+f"(c[1]), "+f"(c[2]), "+f"(c[3])
        : "r"(a[0]), "r"(a[1]), "r"(a[2]), "r"(a[3]), "r"(b[0]), "r"(b[1]));
#endif
}
__device__ __forceinline__ void cp_async16_fb(void* smem, const void* gmem) {
#if defined(__CUDA_ARCH__)
    uint32_t s = (uint32_t)__cvta_generic_to_shared(smem);
    asm volatile("cp.async.cg.shared.global [%0], [%1], 16;\n" :: "r"(s), "l"(gmem));
#endif
}

extern __shared__ char smem_raw_fb[];

__global__ void __launch_bounds__(FB_NTHR, 1) clip_gemm_fb() {
#if !HAS_TC && defined(__CUDA_ARCH__)
    const int dir = blockIdx.x >> 7;
    const int rb  = blockIdx.x & 127;
    const __nv_bfloat16* __restrict__ A = dir ? g_txt_bf : g_img_bf;
    const __nv_bfloat16* __restrict__ B = dir ? g_img_bf : g_txt_bf;

    __nv_bfloat16* As = (__nv_bfloat16*)smem_raw_fb;
    __nv_bfloat16* Bs = As + FB_BM * FB_LDA;
    float2* sm_merge  = (float2*)(Bs + 2 * FB_BN * FB_LDB);

    const int tid  = threadIdx.x;
    const int warp = tid >> 5, lane = tid & 31;
    const int warpM = warp >> 2, warpN = warp & 3;
    const int g = lane >> 2, q = lane & 3;

    {
        const uint4* src = (const uint4*)(A + (size_t)rb * FB_BM * DIM);
        #pragma unroll
        for (int idx = tid; idx < FB_BM * DIM / 8; idx += FB_NTHR) {
            int row = idx >> 6, c8 = idx & 63;
            *(uint4*)(As + row * FB_LDA + c8 * 8) = src[idx];
        }
    }

    auto load_tile = [&](int s, int buf) {
        int jt = s >> 3, kc = s & 7;
        const __nv_bfloat16* bsrc = B + (size_t)(jt * FB_BN) * DIM + kc * 64;
        __nv_bfloat16* dst = Bs + buf * FB_BN * FB_LDB;
        #pragma unroll
        for (int i = tid; i < FB_BN * 8; i += FB_NTHR) {
            int row = i >> 3, c8 = i & 7;
            cp_async16_fb(dst + row * FB_LDB + c8 * 8, bsrc + (size_t)row * DIM + c8 * 8);
        }
        asm volatile("cp.async.commit_group;\n");
    };

    float acc[4][4][4];
    float m_run[8], s_run[8];
    #pragma unroll
    for (int e = 0; e < 8; e++) { m_run[e] = -INFINITY; s_run[e] = 0.f; }

    load_tile(0, 0);

    const int NSTEPS = 128 * 8;
    for (int s = 0; s < NSTEPS; s++) {
        const int buf = s & 1;
        if (s + 1 < NSTEPS) {
            load_tile(s + 1, (s + 1) & 1);
            asm volatile("cp.async.wait_group 1;\n");
        } else {
            asm volatile("cp.async.wait_group 0;\n");
        }
        __syncthreads();

        const int kc = s & 7;
        if (kc == 0) {
            #pragma unroll
            for (int mt = 0; mt < 4; mt++)
                #pragma unroll
                for (int nt = 0; nt < 4; nt++)
                    #pragma unroll
                    for (int r = 0; r < 4; r++) acc[mt][nt][r] = 0.f;
        }

        const __nv_bfloat16* Bb = Bs + buf * FB_BN * FB_LDB;
        #pragma unroll
        for (int kk = 0; kk < 4; kk++) {
            uint32_t af[4][4], bf[4][2];
            const int cA = kc * 64 + kk * 16 + q * 2;
            #pragma unroll
            for (int mt = 0; mt < 4; mt++) {
                const __nv_bfloat16* p = As + (warpM * 64 + mt * 16 + g) * FB_LDA + cA;
                af[mt][0] = *(const uint32_t*)p;
                af[mt][1] = *(const uint32_t*)(p + 8 * FB_LDA);
                af[mt][2] = *(const uint32_t*)(p + 8);
                af[mt][3] = *(const uint32_t*)(p + 8 * FB_LDA + 8);
            }
            const int cB = kk * 16 + q * 2;
            #pragma unroll
            for (int nt = 0; nt < 4; nt++) {
                const __nv_bfloat16* p = Bb + (warpN * 32 + nt * 8 + g) * FB_LDB + cB;
                bf[nt][0] = *(const uint32_t*)p;
                bf[nt][1] = *(const uint32_t*)(p + 8);
            }
            #pragma unroll
            for (int mt = 0; mt < 4; mt++)
                #pragma unroll
                for (int nt = 0; nt < 4; nt++)
                    mma_bf16_fb(acc[mt][nt], af[mt], bf[nt]);
        }
        __syncthreads();

        if (kc == 7) {
            #pragma unroll
            for (int mt = 0; mt < 4; mt++) {
                #pragma unroll
                for (int half = 0; half < 2; half++) {
                    const int e = mt * 2 + half;
                    float v[8];
                    #pragma unroll
                    for (int nt = 0; nt < 4; nt++) {
                        v[nt * 2]     = acc[mt][nt][half * 2]     * SCALEF;
                        v[nt * 2 + 1] = acc[mt][nt][half * 2 + 1] * SCALEF;
                    }
                    float tm = v[0];
                    #pragma unroll
                    for (int i = 1; i < 8; i++) tm = fmaxf(tm, v[i]);
                    const float nm = fmaxf(m_run[e], tm);
                    float ts = 0.f;
                    #pragma unroll
                    for (int i = 0; i < 8; i++) ts += __expf(v[i] - nm);
                    s_run[e] = s_run[e] * __expf(m_run[e] - nm) + ts;
                    m_run[e] = nm;
                }
            }
        }
    }

    #pragma unroll
    for (int e = 0; e < 8; e++) {
        float m = m_run[e], sv = s_run[e];
        #pragma unroll
        for (int o = 1; o < 4; o <<= 1) {
            float mo = __shfl_xor_sync(0xFFFFFFFFu, m, o);
            float so = __shfl_xor_sync(0xFFFFFFFFu, sv, o);
            float nm = fmaxf(m, mo);
            sv = sv * __expf(m - nm) + so * __expf(mo - nm);
            m = nm;
        }
        m_run[e] = m; s_run[e] = sv;
    }

    if (q == 0) {
        #pragma unroll
        for (int e = 0; e < 8; e++) {
            int r = warpM * 64 + (e >> 1) * 16 + (e & 1) * 8 + g;
            sm_merge[r * 4 + warpN] = make_float2(m_run[e], s_run[e]);
        }
    }
    __syncthreads();
    if (tid < 128) {
        float m = -INFINITY, sv = 0.f;
        #pragma unroll
        for (int w = 0; w < 4; w++) {
            float2 ms = sm_merge[tid * 4 + w];
            float nm = fmaxf(m, ms.x);
            sv = sv * __expf(m - nm) + ms.y * __expf(ms.x - nm);
            m = nm;
        }
        g_lse[dir * N_ROWS + rb * FB_BM + tid] = m + __logf(sv);
    }
#endif  // !HAS_TC
}

// ================= final reduction (deterministic) =================
__global__ void reduce1_kernel() {
    __shared__ double sm[256];
    const int base = blockIdx.x * 512;
    double p = 0.0;
    for (int k = threadIdx.x; k < 512; k += 256) {
        const int i = base + k;
        p += (double)g_lse[i] + (double)g_lse[N_ROWS + i] - 2.0 * (double)g_diag[i];
    }
    sm[threadIdx.x] = p;
    __syncthreads();
    for (int o = 128; o; o >>= 1) {
        if (threadIdx.x < o) sm[threadIdx.x] += sm[threadIdx.x + o];
        __syncthreads();
    }
    if (threadIdx.x == 0) g_part[blockIdx.x] = sm[0];
}

__global__ void reduce2_kernel(float* __restrict__ out) {
    double p = g_part[threadIdx.x];
    #pragma unroll
    for (int o = 16; o; o >>= 1) p += __shfl_xor_sync(0xFFFFFFFFu, p, o);
    if (threadIdx.x == 0) out[0] = (float)(p / (2.0 * N_ROWS));
}

// ================= host =================
typedef CUresult (*EncodeTiledFn)(CUtensorMap*, CUtensorMapDataType, cuuint32_t, void*,
                                  const cuuint64_t*, const cuuint64_t*, const cuuint32_t*,
                                  const cuuint32_t*, CUtensorMapInterleave, CUtensorMapSwizzle,
                                  CUtensorMapL2promotion, CUtensorMapFloatOOBfill);

static void make_map(EncodeTiledFn fn, CUtensorMap* m, void* ptr) {
    cuuint64_t dims[3]    = {DIM, N_ROWS, 1};
    cuuint64_t strides[2] = {DIM * 2ull, (cuuint64_t)N_ROWS * DIM * 2ull};
    cuuint32_t box[3]     = {64, 64, 1};
    cuuint32_t es[3]      = {1, 1, 1};
    fn(m, CU_TENSOR_MAP_DATA_TYPE_BFLOAT16, 3, ptr, dims, strides, box, es,
       CU_TENSOR_MAP_INTERLEAVE_NONE, CU_TENSOR_MAP_SWIZZLE_128B,
       CU_TENSOR_MAP_L2_PROMOTION_L2_128B, CU_TENSOR_MAP_FLOAT_OOB_FILL_NONE);
}

extern "C" void kernel_launch(void* const* d_in, const int* in_sizes, int n_in,
                              void* d_out, int out_size) {
    const float* img = (const float*)d_in[0];
    const float* txt = (const float*)d_in[1];

    convert_kernel<<<1024, 256>>>(img, txt);
    diag_kernel<<<2048, 256>>>(img, txt);

    void* pimg = nullptr; void* ptxt = nullptr;
    cudaGetSymbolAddress(&pimg, g_img_bf);
    cudaGetSymbolAddress(&ptxt, g_txt_bf);

    EncodeTiledFn enc = nullptr;
    cudaDriverEntryPointQueryResult qr;
    cudaGetDriverEntryPointByVersion("cuTensorMapEncodeTiled", (void**)&enc, 12000,
                                     cudaEnableDefault, &qr);
    CUtensorMap tm_img, tm_txt;
    make_map(enc, &tm_img, pimg);
    make_map(enc, &tm_txt, ptxt);

    cudaFuncSetAttribute(clip_gemm_tc,
                         cudaFuncAttributeMaxDynamicSharedMemorySize, SMEM_TOTAL_TC);
    clip_gemm_tc<<<256, NTHR, SMEM_TOTAL_TC>>>(tm_img, tm_txt);

    cudaFuncSetAttribute(clip_gemm_fb,
                         cudaFuncAttributeMaxDynamicSharedMemorySize, (int)SMEM_TOTAL_FB);
    clip_gemm_fb<<<256, FB_NTHR, SMEM_TOTAL_FB>>>();

    reduce1_kernel<<<32, 256>>>();
    reduce2_kernel<<<1, 32>>>((float*)d_out);
}